// round 13
// baseline (speedup 1.0000x reference)
#include <cuda_runtime.h>
#include <cuda_bf16.h>
#include <cstdint>
#include <cstddef>

#define DEVI __device__ __forceinline__

// ---------------- scratch (device globals; no allocation) ----------------
__device__ float g_V[8192 * 64];                 // stage-1 output
__device__ float g_H[(size_t)8192 * 4096];       // stage-2 output (tf32, K-permuted)
__device__ float g_Wnr[(size_t)4096 * 4096];     // Wn (tf32, K-permuted)

// K-permutation (within each 32-col block): stored position 4l+j holds
// original column j*8+l. So a thread's 4 per-ks fragment values (cols
// ks*8+t, ks=0..3) are contiguous: float4 at position 4t.

// ---------------- helpers ----------------
DEVI float to_tf32(float x) {
    uint32_t u;
    asm("cvt.rna.tf32.f32 %0, %1;" : "=r"(u) : "f"(x));
    return __uint_as_float(u);
}
DEVI uint32_t smem_u32(const void* p) {
    uint32_t a;
    asm("{ .reg .u64 t; cvta.to.shared.u64 t, %1; cvt.u32.u64 %0, t; }" : "=r"(a) : "l"(p));
    return a;
}
DEVI void cp16(uint32_t saddr, const void* gaddr) {
    asm volatile("cp.async.cg.shared.global [%0], [%1], 16;" :: "r"(saddr), "l"(gaddr) : "memory");
}
DEVI void cp_commit() { asm volatile("cp.async.commit_group;" ::: "memory"); }
DEVI void cp_wait0()  { asm volatile("cp.async.wait_group 0;" ::: "memory"); }
DEVI void cp_wait1()  { asm volatile("cp.async.wait_group 1;" ::: "memory"); }

DEVI void mma8(float c[4], const uint32_t a[4], const uint32_t b[2]) {
    asm("mma.sync.aligned.m16n8k8.row.col.f32.tf32.tf32.f32 "
        "{%0,%1,%2,%3}, {%4,%5,%6,%7}, {%8,%9}, {%0,%1,%2,%3};\n"
        : "+f"(c[0]), "+f"(c[1]), "+f"(c[2]), "+f"(c[3])
        : "r"(a[0]), "r"(a[1]), "r"(a[2]), "r"(a[3]),
          "r"(b[0]), "r"(b[1]));
}

// ============================================================================
// Stage 3: out[8192,4096] = relu( H @ Wn^T + bn )
// mma.sync tf32. 128x256 CTA tile, 64x64 warp tiles, K-tile 32, double buffer.
// Operands pre-rounded AND K-permuted; vectorized LDS.128 fragment loads.
// ============================================================================
static constexpr int S3_AS = 128 * 32;             // A stage floats (16 KB)
static constexpr int S3_BS = 256 * 32;             // B stage floats (32 KB)
static constexpr int S3_SMEM = 2 * (S3_AS + S3_BS) * (int)sizeof(float);  // 96 KB

DEVI void s3_fill(float* As, float* Bs,
                  const float* __restrict__ A, const float* __restrict__ B,
                  int bm, int bn, int k0, int tid)
{
#pragma unroll
    for (int i = 0; i < 4; ++i) {                   // A: 128 rows x 8 chunks
        const int ch = tid + (i << 8);
        const int r = ch >> 3, c4 = ch & 7;
        const int dst = r * 32 + ((c4 ^ ((r & 1) << 2)) << 2);
        cp16(smem_u32(As + dst), A + ((size_t)(bm * 128 + r) << 12) + k0 + (c4 << 2));
    }
#pragma unroll
    for (int i = 0; i < 8; ++i) {                   // B: 256 rows x 8 chunks
        const int ch = tid + (i << 8);
        const int r = ch >> 3, c4 = ch & 7;
        const int dst = r * 32 + ((c4 ^ ((r & 1) << 2)) << 2);
        cp16(smem_u32(Bs + dst), B + ((size_t)(bn * 256 + r) << 12) + k0 + (c4 << 2));
    }
}

__global__ void __launch_bounds__(256, 1)
gemm3_mma(const float* __restrict__ A,    // g_H   (tf32, permuted)
          const float* __restrict__ B,    // g_Wnr (tf32, permuted)
          const float* __restrict__ bias,
          float* __restrict__ C)
{
    constexpr int NK = 128;                         // 4096 / 32
    extern __shared__ float smem[];
    float* const Asb[2] = { smem, smem + S3_AS };
    float* const Bsb[2] = { smem + 2 * S3_AS, smem + 2 * S3_AS + S3_BS };

    const int tid  = threadIdx.x;
    const int lane = tid & 31;
    const int wid  = tid >> 5;
    const int g    = lane >> 2;
    const int tig  = lane & 3;
    const int wm   = (wid >> 2) * 64;
    const int wn   = (wid & 3) * 64;
    const int bn = blockIdx.x, bm = blockIdx.y;
    const int s4 = (g & 1) << 2;                    // phase swizzle for this lane's rows
    const int cL = ((tig     ) ^ s4) << 2;          // low-chunk float offset
    const int cH = ((tig + 4) ^ s4) << 2;           // high-chunk float offset

    float acc[4][8][4];
#pragma unroll
    for (int mt = 0; mt < 4; ++mt)
#pragma unroll
        for (int nt = 0; nt < 8; ++nt)
#pragma unroll
            for (int i = 0; i < 4; ++i) acc[mt][nt][i] = 0.f;

    s3_fill(Asb[0], Bsb[0], A, B, bm, bn, 0,  tid); cp_commit();
    s3_fill(Asb[1], Bsb[1], A, B, bm, bn, 32, tid); cp_commit();

    for (int kt = 0; kt < NK; ++kt) {
        const int s = kt & 1;
        if (kt == NK - 1) cp_wait0(); else cp_wait1();
        __syncthreads();

        const float* __restrict__ Ac = Asb[s];
        const float* __restrict__ Bc = Bsb[s];

        // B fragments resident: 8 nt x 2 float4 (each float4 = 4 ks values)
        float4 bv0[8], bv1[8];
#pragma unroll
        for (int nt = 0; nt < 8; ++nt) {
            const int rb = (wn + nt * 8 + g) * 32;
            bv0[nt] = *(const float4*)&Bc[rb + cL];
            bv1[nt] = *(const float4*)&Bc[rb + cH];
        }

#pragma unroll
        for (int mt = 0; mt < 4; ++mt) {
            const int r0 = (wm + mt * 16 + g) * 32;
            const int r1 = r0 + 8 * 32;
            const float4 a0 = *(const float4*)&Ac[r0 + cL];
            const float4 a1 = *(const float4*)&Ac[r1 + cL];
            const float4 a2 = *(const float4*)&Ac[r0 + cH];
            const float4 a3 = *(const float4*)&Ac[r1 + cH];
#pragma unroll
            for (int ks = 0; ks < 4; ++ks) {
                uint32_t af[4];
                af[0] = __float_as_uint(((const float*)&a0)[ks]);
                af[1] = __float_as_uint(((const float*)&a1)[ks]);
                af[2] = __float_as_uint(((const float*)&a2)[ks]);
                af[3] = __float_as_uint(((const float*)&a3)[ks]);
#pragma unroll
                for (int nt = 0; nt < 8; ++nt) {
                    uint32_t bf[2];
                    bf[0] = __float_as_uint(((const float*)&bv0[nt])[ks]);
                    bf[1] = __float_as_uint(((const float*)&bv1[nt])[ks]);
                    mma8(acc[mt][nt], af, bf);
                }
            }
        }

        __syncthreads();
        const int nt2 = kt + 2;
        if (nt2 < NK) {
            s3_fill(Asb[s], Bsb[s], A, B, bm, bn, nt2 * 32, tid);
            cp_commit();
        }
    }

    // epilogue: bias + relu (output in ORIGINAL layout)
#pragma unroll
    for (int mt = 0; mt < 4; ++mt) {
#pragma unroll
        for (int nt = 0; nt < 8; ++nt) {
            const int m = bm * 128 + wm + mt * 16 + g;
            const int n = bn * 256 + wn + nt * 8 + 2 * tig;
            const float2 bb = *(const float2*)(bias + n);
            float2 v0, v1;
            v0.x = fmaxf(acc[mt][nt][0] + bb.x, 0.f);
            v0.y = fmaxf(acc[mt][nt][1] + bb.y, 0.f);
            v1.x = fmaxf(acc[mt][nt][2] + bb.x, 0.f);
            v1.y = fmaxf(acc[mt][nt][3] + bb.y, 0.f);
            *(float2*)(C + ((size_t)m << 12) + n)       = v0;
            *(float2*)(C + ((size_t)(m + 8) << 12) + n) = v1;
        }
    }
}

// ============================================================================
// Permute+round pass: Wn -> g_Wnr (tf32, K-permuted within 32-col blocks)
// out[r][b*32 + 4l + j] = round(in[r][b*32 + j*8 + l])
// ============================================================================
__global__ void perm_round_kernel(const float* __restrict__ in, float* __restrict__ out)
{
    const int total = 4096 * 1024;                  // one thread-task per float4
    for (int idx = blockIdx.x * blockDim.x + threadIdx.x; idx < total;
         idx += gridDim.x * blockDim.x) {
        const int l = idx & 7;
        const int b = (idx >> 3) & 127;
        const int r = idx >> 10;
        const float* src = in + ((size_t)r << 12) + b * 32 + l;
        float4 v;
        v.x = to_tf32(src[0]);
        v.y = to_tf32(src[8]);
        v.z = to_tf32(src[16]);
        v.w = to_tf32(src[24]);
        *(float4*)(out + ((size_t)r << 12) + b * 32 + 4 * l) = v;
    }
}

// ============================================================================
// V init: V[m][n] = bv[n]  (8192 x 64)
// ============================================================================
__global__ void init_bias_kernel(float4* __restrict__ V, const float4* __restrict__ bv)
{
    for (int i = blockIdx.x * blockDim.x + threadIdx.x; i < 131072; i += gridDim.x * blockDim.x)
        V[i] = bv[i & 15];
}

// ============================================================================
// Stages 1-2: mma.sync tf32 GEMM
// EPI: 1 = +bias +resid, round, ORIGINAL layout (unused now)
//      2 = +bias +resid, round, K-PERMUTED output layout (stage 2 -> g_H)
//      3 = split-K atomicAdd (stage 1)
// ============================================================================
template <int BM, int BN, int EPI>
__global__ void __launch_bounds__(256, 1)
gemm_tf32_kernel(const float* __restrict__ A,
                 const float* __restrict__ B,
                 const float* __restrict__ bias,
                 const float* __restrict__ resid,
                 float* __restrict__ C,
                 int M, int N, int Klen, int ldk)
{
    constexpr int MT = BM / 32;
    constexpr int NT = BN / 32;
    constexpr int LD = 36;

    extern __shared__ float smemf[];
    float* const As0 = smemf;
    float* const As1 = smemf + BM * LD;
    float* const Bs0 = smemf + 2 * BM * LD;
    float* const Bs1 = smemf + 2 * BM * LD + BN * LD;
    float* const Asb[2] = { As0, As1 };
    float* const Bsb[2] = { Bs0, Bs1 };

    const int tid  = threadIdx.x;
    const int lane = tid & 31;
    const int wid  = tid >> 5;
    const int g    = lane >> 2;
    const int tig  = lane & 3;

    const int wm = (wid >> 2) * (BM / 2);
    const int wn = (wid & 3) * (BN / 4);

    const size_t koff = (size_t)blockIdx.z * Klen;
    const float* Ab = A + (size_t)blockIdx.y * BM * ldk + koff;
    const float* Bb = B + (size_t)blockIdx.x * BN * ldk + koff;

    const int lr = tid >> 3;
    const int lc = (tid & 7) * 4;

    float4 ra[MT], rb[NT];
    float acc[MT][NT][4];
#pragma unroll
    for (int mt = 0; mt < MT; ++mt)
#pragma unroll
        for (int nt = 0; nt < NT; ++nt)
#pragma unroll
            for (int i = 0; i < 4; ++i) acc[mt][nt][i] = 0.f;

    const int ktiles = Klen >> 5;

#pragma unroll
    for (int i = 0; i < MT; ++i)
        ra[i] = *(const float4*)(Ab + (size_t)(lr + 32 * i) * ldk + lc);
#pragma unroll
    for (int i = 0; i < NT; ++i)
        rb[i] = *(const float4*)(Bb + (size_t)(lr + 32 * i) * ldk + lc);
#pragma unroll
    for (int i = 0; i < MT; ++i) {
        float4 t = ra[i];
        t.x = to_tf32(t.x); t.y = to_tf32(t.y); t.z = to_tf32(t.z); t.w = to_tf32(t.w);
        *(float4*)&As0[(lr + 32 * i) * LD + lc] = t;
    }
#pragma unroll
    for (int i = 0; i < NT; ++i) {
        float4 t = rb[i];
        t.x = to_tf32(t.x); t.y = to_tf32(t.y); t.z = to_tf32(t.z); t.w = to_tf32(t.w);
        *(float4*)&Bs0[(lr + 32 * i) * LD + lc] = t;
    }
    __syncthreads();

    for (int kt = 0; kt < ktiles; ++kt) {
        const int cur = kt & 1;
        const bool more = (kt + 1) < ktiles;

        if (more) {
            const int ko = (kt + 1) * 32;
#pragma unroll
            for (int i = 0; i < MT; ++i)
                ra[i] = *(const float4*)(Ab + (size_t)(lr + 32 * i) * ldk + ko + lc);
#pragma unroll
            for (int i = 0; i < NT; ++i)
                rb[i] = *(const float4*)(Bb + (size_t)(lr + 32 * i) * ldk + ko + lc);
        }

        const float* __restrict__ Ac = Asb[cur];
        const float* __restrict__ Bc = Bsb[cur];
#pragma unroll
        for (int ks = 0; ks < 4; ++ks) {
            uint32_t af[MT][4];
            uint32_t bf[NT][2];
            const int c0 = ks * 8 + tig;
#pragma unroll
            for (int mt = 0; mt < MT; ++mt) {
                const int r0 = wm + mt * 16 + g;
                af[mt][0] = __float_as_uint(Ac[r0 * LD + c0]);
                af[mt][1] = __float_as_uint(Ac[(r0 + 8) * LD + c0]);
                af[mt][2] = __float_as_uint(Ac[r0 * LD + c0 + 4]);
                af[mt][3] = __float_as_uint(Ac[(r0 + 8) * LD + c0 + 4]);
            }
#pragma unroll
            for (int nt = 0; nt < NT; ++nt) {
                const int r0 = wn + nt * 8 + g;
                bf[nt][0] = __float_as_uint(Bc[r0 * LD + c0]);
                bf[nt][1] = __float_as_uint(Bc[r0 * LD + c0 + 4]);
            }
#pragma unroll
            for (int mt = 0; mt < MT; ++mt)
#pragma unroll
                for (int nt = 0; nt < NT; ++nt)
                    mma8(acc[mt][nt], af[mt], bf[nt]);
        }

        if (more) {
            float* const An = Asb[cur ^ 1];
            float* const Bn = Bsb[cur ^ 1];
#pragma unroll
            for (int i = 0; i < MT; ++i) {
                float4 t = ra[i];
                t.x = to_tf32(t.x); t.y = to_tf32(t.y); t.z = to_tf32(t.z); t.w = to_tf32(t.w);
                *(float4*)&An[(lr + 32 * i) * LD + lc] = t;
            }
#pragma unroll
            for (int i = 0; i < NT; ++i) {
                float4 t = rb[i];
                t.x = to_tf32(t.x); t.y = to_tf32(t.y); t.z = to_tf32(t.z); t.w = to_tf32(t.w);
                *(float4*)&Bn[(lr + 32 * i) * LD + lc] = t;
            }
        }
        __syncthreads();
    }

    const int m0 = blockIdx.y * BM + wm;
    const int n0 = blockIdx.x * BN + wn;

    if (EPI == 2) {
        // permuted write: pos within 32-block = (n%8)*4 + (n%32)/8
        // thread owns cols {2tig+eb + 8nt}: element e across nt = one float4
#pragma unroll
        for (int mt = 0; mt < MT; ++mt) {
            const int m = m0 + mt * 16 + g;
            float4 e0, e1, e2, e3;
#pragma unroll
            for (int nt = 0; nt < NT; ++nt) {
                const int nc = n0 + nt * 8 + 2 * tig;
                const float b0 = bias[nc], b1 = bias[nc + 1];
                const float2 r0 = *(const float2*)(resid + (size_t)m * N + nc);
                const float2 r1 = *(const float2*)(resid + (size_t)(m + 8) * N + nc);
                ((float*)&e0)[nt] = to_tf32(acc[mt][nt][0] + b0 + r0.x);
                ((float*)&e1)[nt] = to_tf32(acc[mt][nt][1] + b1 + r0.y);
                ((float*)&e2)[nt] = to_tf32(acc[mt][nt][2] + b0 + r1.x);
                ((float*)&e3)[nt] = to_tf32(acc[mt][nt][3] + b1 + r1.y);
            }
            float* c0p = C + (size_t)m * N + n0 + 8 * tig;
            float* c1p = C + (size_t)(m + 8) * N + n0 + 8 * tig;
            *(float4*)(c0p)     = e0;
            *(float4*)(c0p + 4) = e1;
            *(float4*)(c1p)     = e2;
            *(float4*)(c1p + 4) = e3;
        }
    } else {
#pragma unroll
        for (int mt = 0; mt < MT; ++mt) {
#pragma unroll
            for (int nt = 0; nt < NT; ++nt) {
                const int m = m0 + mt * 16 + g;
                const int n = n0 + nt * 8 + 2 * tig;
                if (EPI == 3) {
                    atomicAdd(C + (size_t)m * N + n,           acc[mt][nt][0]);
                    atomicAdd(C + (size_t)m * N + n + 1,       acc[mt][nt][1]);
                    atomicAdd(C + (size_t)(m + 8) * N + n,     acc[mt][nt][2]);
                    atomicAdd(C + (size_t)(m + 8) * N + n + 1, acc[mt][nt][3]);
                } else {
                    const float2 bb = *(const float2*)(bias + n);
                    float v0 = acc[mt][nt][0] + bb.x;
                    float v1 = acc[mt][nt][1] + bb.y;
                    float v2 = acc[mt][nt][2] + bb.x;
                    float v3 = acc[mt][nt][3] + bb.y;
                    if (EPI == 1) {
                        const float2 r0 = *(const float2*)(resid + (size_t)m * N + n);
                        const float2 r1 = *(const float2*)(resid + (size_t)(m + 8) * N + n);
                        v0 = to_tf32(v0 + r0.x); v1 = to_tf32(v1 + r0.y);
                        v2 = to_tf32(v2 + r1.x); v3 = to_tf32(v3 + r1.y);
                    }
                    *(float2*)(C + (size_t)m * N + n)       = make_float2(v0, v1);
                    *(float2*)(C + (size_t)(m + 8) * N + n) = make_float2(v2, v3);
                }
            }
        }
    }
}

// ============================================================================
// launch
// Inputs (metadata order): x, Wq, bq, Wk, bk, Wv, bv, Wo, bo, Wn, bn
// Singleton softmax => attended == v; Wq/bq/Wk/bk dead.
// ============================================================================
extern "C" void kernel_launch(void* const* d_in, const int* in_sizes, int n_in,
                              void* d_out, int out_size)
{
    const float* x  = (const float*)d_in[0];
    const float* Wv = (const float*)d_in[5];
    const float* bv = (const float*)d_in[6];
    const float* Wo = (const float*)d_in[7];
    const float* bo = (const float*)d_in[8];
    const float* Wn = (const float*)d_in[9];
    const float* bn = (const float*)d_in[10];
    float* out = (float*)d_out;

    float *V = nullptr, *H = nullptr, *Wnr = nullptr;
    cudaGetSymbolAddress((void**)&V,   g_V);
    cudaGetSymbolAddress((void**)&H,   g_H);
    cudaGetSymbolAddress((void**)&Wnr, g_Wnr);

    constexpr int SM64  = 2 * (64 + 64)   * 36 * (int)sizeof(float);
    constexpr int SM128 = 2 * (128 + 128) * 36 * (int)sizeof(float);

    cudaFuncSetAttribute(gemm_tf32_kernel<64, 64, 3>,
                         cudaFuncAttributeMaxDynamicSharedMemorySize, SM64);
    cudaFuncSetAttribute(gemm_tf32_kernel<128, 128, 2>,
                         cudaFuncAttributeMaxDynamicSharedMemorySize, SM128);
    cudaFuncSetAttribute(gemm3_mma,
                         cudaFuncAttributeMaxDynamicSharedMemorySize, S3_SMEM);

    // Wn -> tf32-rounded, K-permuted copy
    perm_round_kernel<<<4096, 256>>>(Wn, Wnr);

    // Stage 1: V = bv ; V += x @ Wv^T  (split-K x4, atomicAdd)
    init_bias_kernel<<<512, 256>>>((float4*)V, (const float4*)bv);
    gemm_tf32_kernel<64, 64, 3><<<dim3(1, 128, 4), 256, SM64>>>(
        x, Wv, nullptr, nullptr, V, 8192, 64, 1024, 4096);

    // Stage 2: H = perm( round_tf32( V @ Wo^T + bo + x ) )
    gemm_tf32_kernel<128, 128, 2><<<dim3(32, 64, 1), 256, SM128>>>(
        V, Wo, bo, x, H, 8192, 4096, 64, 64);

    // Stage 3: out = relu(H @ Wn^T + bn) — vectorized fragment loads
    gemm3_mma<<<dim3(16, 64), 256, S3_SMEM>>>(H, Wnr, bn, out);
}